// round 5
// baseline (speedup 1.0000x reference)
#include <cuda_runtime.h>

// Soft-argmax: input (B=4, C=14, H=1024, W=1024) fp32 NCHW.
// Output (4, 2, 1024, 1024) fp32.
//
// R4: persistent grid-stride kernel (148 SMs x 4 CTAs, exactly one wave) —
// eliminates wave-transition DRAM-queue drains. Per-iteration body identical
// to R2: 14 front-batched streaming LDG.128, 8x soft1, 2 streaming STG.128.

#define HW      (1024 * 1024)
#define HWQ     (HW / 4)          // 262144 = 2^18 quads per plane
#define HWQ_LOG 18
#define C_IN    14
#define B       4

#define NBLOCKS 592               // 148 SMs * 4 resident CTAs
#define NTHREADS 256
#define STRIDE  (NBLOCKS * NTHREADS)   // 151552
#define TOTAL   (B * HWQ)              // 1048576

__device__ __forceinline__ float soft1(float a0, float a1, float a2, float a3,
                                       float a4, float a5, float a6) {
    float e0 = __expf(a0);
    float e1 = __expf(a1);
    float e2 = __expf(a2);
    float e3 = __expf(a3);
    float e4 = __expf(a4);
    float e5 = __expf(a5);
    float e6 = __expf(a6);
    float den = ((e0 + e1) + (e2 + e3)) + ((e4 + e5) + e6);
    float pos = fmaf(3.0f, e6, fmaf(2.0f, e5, e4));
    float neg = fmaf(3.0f, e0, fmaf(2.0f, e1, e2));
    return __fdividef(pos - neg, den);
}

__global__ __launch_bounds__(NTHREADS, 4)
void softargmax_kernel(const float4* __restrict__ x, float4* __restrict__ out) {
    int q0 = blockIdx.x * NTHREADS + threadIdx.x;

    // TOTAL/STRIDE = 6.92 -> 7 iterations, last one predicated.
    for (int q = q0; q < TOTAL; q += STRIDE) {
        int b = q >> HWQ_LOG;
        int s = q & (HWQ - 1);

        const float4* in = x + (size_t)b * C_IN * HWQ + s;

        float4 v[C_IN];
#pragma unroll
        for (int c = 0; c < C_IN; c++) {
            v[c] = __ldcs(&in[(size_t)c * HWQ]);   // front-batched, streaming
        }

        const float* f = reinterpret_cast<const float*>(v);  // f[c*4 + lane]

        float4 r0, r1;
        float* o0 = reinterpret_cast<float*>(&r0);
        float* o1 = reinterpret_cast<float*>(&r1);

#pragma unroll
        for (int l = 0; l < 4; l++) {
            o0[l] = soft1(f[0*4+l], f[1*4+l], f[2*4+l], f[3*4+l],
                          f[4*4+l], f[5*4+l], f[6*4+l]);
            o1[l] = soft1(f[7*4+l], f[8*4+l], f[9*4+l], f[10*4+l],
                          f[11*4+l], f[12*4+l], f[13*4+l]);
        }

        float4* ob = out + (size_t)b * 2 * HWQ + s;
        __stcs(&ob[0],   r0);
        __stcs(&ob[HWQ], r1);
    }
}

extern "C" void kernel_launch(void* const* d_in, const int* in_sizes, int n_in,
                              void* d_out, int out_size) {
    const float4* x = (const float4*)d_in[0];
    float4* out = (float4*)d_out;

    softargmax_kernel<<<NBLOCKS, NTHREADS>>>(x, out);
}

// round 10
// speedup vs baseline: 1.1042x; 1.1042x over previous
#include <cuda_runtime.h>

// Soft-argmax: input (B=4, C=14, H=1024, W=1024) fp32 NCHW.
// Output (4, 2, 1024, 1024) fp32.
//
// R5 (resubmit after infra failure): process the two K=7 channel groups
// sequentially per thread. Each group needs only 7 front-batched streaming
// LDG.128 (28 payload regs), so the kernel fits ~40 regs -> 6 CTAs/SM
// (75% occ) while keeping clean MLP=7 batches and ldcs/stcs streaming policy.

#define HW      (1024 * 1024)
#define HWQ     (HW / 4)          // 262144 = 2^18 quads per plane
#define HWQ_LOG 18
#define C_IN    14
#define K       7
#define B       4

__device__ __forceinline__ float soft1(float a0, float a1, float a2, float a3,
                                       float a4, float a5, float a6) {
    float e0 = __expf(a0);
    float e1 = __expf(a1);
    float e2 = __expf(a2);
    float e3 = __expf(a3);
    float e4 = __expf(a4);
    float e5 = __expf(a5);
    float e6 = __expf(a6);
    float den = ((e0 + e1) + (e2 + e3)) + ((e4 + e5) + e6);
    float pos = fmaf(3.0f, e6, fmaf(2.0f, e5, e4));
    float neg = fmaf(3.0f, e0, fmaf(2.0f, e1, e2));
    return __fdividef(pos - neg, den);
}

__device__ __forceinline__ float4 group7(const float4* __restrict__ in) {
    float4 v[K];
#pragma unroll
    for (int c = 0; c < K; c++) {
        v[c] = __ldcs(&in[(size_t)c * HWQ]);   // 7 front-batched streaming loads
    }
    const float* f = reinterpret_cast<const float*>(v);  // f[c*4 + lane]
    float4 r;
    float* o = reinterpret_cast<float*>(&r);
#pragma unroll
    for (int l = 0; l < 4; l++) {
        o[l] = soft1(f[0*4+l], f[1*4+l], f[2*4+l], f[3*4+l],
                     f[4*4+l], f[5*4+l], f[6*4+l]);
    }
    return r;
}

__global__ __launch_bounds__(256, 6)
void softargmax_kernel(const float4* __restrict__ x, float4* __restrict__ out) {
    int q = blockIdx.x * blockDim.x + threadIdx.x;   // [0, B*HWQ)
    int b = q >> HWQ_LOG;
    int s = q & (HWQ - 1);

    const float4* in = x + (size_t)b * C_IN * HWQ + s;
    float4* ob = out + (size_t)b * 2 * HWQ + s;

    // Group 0: channels 0..6 -> out channel 0
    float4 r0 = group7(in);
    __stcs(&ob[0], r0);

    // Group 1: channels 7..13 -> out channel 1
    float4 r1 = group7(in + (size_t)K * HWQ);
    __stcs(&ob[HWQ], r1);
}

extern "C" void kernel_launch(void* const* d_in, const int* in_sizes, int n_in,
                              void* d_out, int out_size) {
    const float4* x = (const float4*)d_in[0];
    float4* out = (float4*)d_out;

    const int total_quads = B * HWQ;          // 1,048,576
    const int threads = 256;
    const int blocks = total_quads / threads; // 4096

    softargmax_kernel<<<blocks, threads>>>(x, out);
}